// round 6
// baseline (speedup 1.0000x reference)
#include <cuda_runtime.h>
#include <cuda_bf16.h>
#include <cstdint>

#define L_SEQ   16384
#define D_MOD   1024
#define H_DIM   1024
#define T_CHUNK 128
#define N_CHUNK 128   // L_SEQ / T_CHUNK

// ---------------- static scratch ----------------
__device__ float g_xr [(size_t)L_SEQ * D_MOD];          // tf32-rounded x
__device__ float g_W1 [(size_t)2 * H_DIM * D_MOD];      // [2048 x 1024] stacked re/im of scaled B (tf32)
__device__ float g_W2 [(size_t)D_MOD * 2 * H_DIM];      // [1024 x 2048] = [Cre | -Cim] (tf32)
__device__ float g_Bu [(size_t)L_SEQ * 2 * H_DIM];      // [16384 x 2048] Bu, then H (tf32) in place
__device__ float g_lre[H_DIM], g_lim[H_DIM];
__device__ float g_lTre[H_DIM], g_lTim[H_DIM];
__device__ float g_Ere[N_CHUNK * H_DIM], g_Eim[N_CHUNK * H_DIM];
__device__ float g_Sre[N_CHUNK * H_DIM], g_Sim[N_CHUNK * H_DIM];

// ---------------- helpers ----------------
__device__ __forceinline__ float tf32r(float x) {     // round-to-nearest tf32
    uint32_t u;
    asm("cvt.rna.tf32.f32 %0, %1;" : "=r"(u) : "f"(x));
    return __uint_as_float(u);
}
__device__ __forceinline__ void cp16(uint32_t dst, const void* src) {
    asm volatile("cp.async.cg.shared.global [%0], [%1], 16;" :: "r"(dst), "l"(src) : "memory");
}
__device__ __forceinline__ void cp_commit() { asm volatile("cp.async.commit_group;" ::: "memory"); }
__device__ __forceinline__ void cp_wait1()  { asm volatile("cp.async.wait_group 1;" ::: "memory"); }
__device__ __forceinline__ void cp_wait0()  { asm volatile("cp.async.wait_group 0;" ::: "memory"); }
__device__ __forceinline__ uint32_t smem_u32(const void* p) {
    uint32_t a;
    asm("{ .reg .u64 t; cvta.to.shared.u64 t, %1; cvt.u32.u64 %0, t; }" : "=r"(a) : "l"(p));
    return a;
}
__device__ __forceinline__ void mma_tf32(float* c, uint32_t a0, uint32_t a1, uint32_t a2, uint32_t a3,
                                         uint32_t b0, uint32_t b1) {
    asm volatile(
        "mma.sync.aligned.m16n8k8.row.col.f32.tf32.tf32.f32 "
        "{%0,%1,%2,%3}, {%4,%5,%6,%7}, {%8,%9}, {%0,%1,%2,%3};\n"
        : "+f"(c[0]), "+f"(c[1]), "+f"(c[2]), "+f"(c[3])
        : "r"(a0), "r"(a1), "r"(a2), "r"(a3), "r"(b0), "r"(b1));
}
// ldmatrix x4 of 8x(4 f32) tiles — tf32 fragment mapping matches m8n8.b16 exactly
__device__ __forceinline__ void ldsm4(uint32_t* r, uint32_t addr) {
    asm volatile("ldmatrix.sync.aligned.m8n8.x4.shared.b16 {%0,%1,%2,%3}, [%4];"
                 : "=r"(r[0]), "=r"(r[1]), "=r"(r[2]), "=r"(r[3]) : "r"(addr));
}

// smem tile geometry: 128 rows x 32 cols, row stride 36 floats (conflict-free: 36 ≡ 4 mod 32)
#define TSTRIDE   36
#define TILE_FLTS (128 * TSTRIDE)            // 4608 floats = 18432 B
#define STAGE_FLTS (2 * TILE_FLTS)           // A tile + B tile
#define SMEM_TOTAL (2 * STAGE_FLTS * 4)      // double buffered = 73728 B

// ---------------- TF32 NT GEMM: O[m,n] = sum_k A[m,k] * W[n,k]  (+ EPI: Dp[n]*X[m,n]) ----------------
// 128x128 block tile, BK=32, 8 warps as 2(m) x 4(n); warp tile 64x32 -> mt=4, nt=4.
template <int EPI>
__global__ __launch_bounds__(256, 2) void mma_gemm(
    const float* __restrict__ A, const float* __restrict__ W,
    float* __restrict__ O, int K, int Nout,
    const float* __restrict__ Dp, const float* __restrict__ X)
{
    extern __shared__ float smem[];
    const uint32_t sbase = smem_u32(smem);
    const int tid = threadIdx.x;
    const int wid = tid >> 5, lane = tid & 31;
    const int g = lane >> 2, tig = lane & 3;
    const int wm = wid & 1, wn = wid >> 1;           // 2 x 4 warps; warp tile 64 x 32
    const int m0 = blockIdx.x * 128, n0 = blockIdx.y * 128;
    const int NC = K >> 5;                           // K chunks of 32

    const int r_ld  = tid >> 1;                      // row loaded by this thread
    const int c4_ld = (tid & 1) * 4;

    auto load_chunk = [&](int stage, int kc) {
        const uint32_t sa = sbase + (uint32_t)(stage * STAGE_FLTS) * 4u;
        const uint32_t sb = sa + (uint32_t)TILE_FLTS * 4u;
        const int kbase = kc * 32;
#pragma unroll
        for (int i = 0; i < 4; i++) {
            int c4 = c4_ld + (i & 3);                // 0..7
            uint32_t doff = (uint32_t)(r_ld * TSTRIDE + c4 * 4) * 4u;
            cp16(sa + doff, A + (size_t)(m0 + r_ld) * K + kbase + c4 * 4);
            cp16(sb + doff, W + (size_t)(n0 + r_ld) * K + kbase + c4 * 4);
        }
    };

    // per-lane ldmatrix base offsets (bytes)
    const int lrow = lane & 7, lj = lane >> 3;
    // A x4 tiles: j0=(+0r,+0c) j1=(+8r,+0c) j2=(+0r,+4c) j3=(+8r,+4c)  -> regs a0..a3
    const uint32_t a_lane = (uint32_t)(((wm * 64 + lrow + (lj & 1) * 8) * TSTRIDE
                                        + (lj >> 1) * 4) * 4);
    // B x4 tiles: j0=(nt rows,+0c) j1=(nt rows,+4c) j2=(nt+1 rows,+0c) j3=(nt+1 rows,+4c)
    const uint32_t b_lane = (uint32_t)(TILE_FLTS * 4
                                       + ((wn * 32 + lrow + (lj >> 1) * 8) * TSTRIDE
                                          + (lj & 1) * 4) * 4);

    float acc[4][4][4];
#pragma unroll
    for (int mt = 0; mt < 4; mt++)
#pragma unroll
        for (int nt = 0; nt < 4; nt++)
#pragma unroll
            for (int q = 0; q < 4; q++) acc[mt][nt][q] = 0.f;

    load_chunk(0, 0);
    cp_commit();

    for (int kc = 0; kc < NC; kc++) {
        if (kc + 1 < NC) {
            load_chunk((kc + 1) & 1, kc + 1);
            cp_commit();
            cp_wait1();
        } else {
            cp_wait0();
        }
        __syncthreads();
        const uint32_t st = sbase + (uint32_t)((kc & 1) * STAGE_FLTS) * 4u;
#pragma unroll
        for (int s = 0; s < 4; s++) {
            const uint32_t koff = (uint32_t)(s * 32);          // 8 floats
            uint32_t af[4][4];
#pragma unroll
            for (int mt = 0; mt < 4; mt++)
                ldsm4(af[mt], st + a_lane + (uint32_t)(mt * 16 * TSTRIDE * 4) + koff);
            uint32_t bf[2][4];
#pragma unroll
            for (int p = 0; p < 2; p++)
                ldsm4(bf[p], st + b_lane + (uint32_t)(p * 16 * TSTRIDE * 4) + koff);
#pragma unroll
            for (int mt = 0; mt < 4; mt++)
#pragma unroll
                for (int nt = 0; nt < 4; nt++)
                    mma_tf32(acc[mt][nt], af[mt][0], af[mt][1], af[mt][2], af[mt][3],
                             bf[nt >> 1][(nt & 1) * 2], bf[nt >> 1][(nt & 1) * 2 + 1]);
        }
        __syncthreads();
    }

    // epilogue
#pragma unroll
    for (int mt = 0; mt < 4; mt++) {
        int row0 = m0 + wm * 64 + mt * 16 + g;
#pragma unroll
        for (int nt = 0; nt < 4; nt++) {
            int col = n0 + wn * 32 + nt * 8 + tig * 2;
            float2 v0 = make_float2(acc[mt][nt][0], acc[mt][nt][1]);
            float2 v1 = make_float2(acc[mt][nt][2], acc[mt][nt][3]);
            if (EPI) {
                float2 dp = *(const float2*)(Dp + col);
                float2 x0 = *(const float2*)(X + (size_t)row0 * 1024 + col);
                float2 x1 = *(const float2*)(X + (size_t)(row0 + 8) * 1024 + col);
                v0.x += dp.x * x0.x; v0.y += dp.y * x0.y;
                v1.x += dp.x * x1.x; v1.y += dp.y * x1.y;
            }
            *(float2*)(O + (size_t)row0 * Nout + col) = v0;
            *(float2*)(O + (size_t)(row0 + 8) * Nout + col) = v1;
        }
    }
}

// ---------------- conversions (tf32 pre-rounding) ----------------
__global__ void conv_x(const float* __restrict__ x) {
    size_t i = (size_t)(blockIdx.x * blockDim.x + threadIdx.x) * 4;
    float4 v = *(const float4*)(x + i);
    v.x = tf32r(v.x); v.y = tf32r(v.y); v.z = tf32r(v.z); v.w = tf32r(v.w);
    *(float4*)(g_xr + i) = v;
}

__global__ void prep_W1(const float* __restrict__ Bre, const float* __restrict__ Bim,
                        const float* __restrict__ gamma_log) {
    int n = blockIdx.x;             // 0..2047
    int h = n & 1023;
    const float* src = (n < 1024) ? Bre : Bim;
    float eg = expf(gamma_log[h]);
#pragma unroll
    for (int j = 0; j < 4; j++) {
        int k = threadIdx.x * 4 + j;
        g_W1[(size_t)n * 1024 + k] = tf32r(src[h * 1024 + k] * eg);
    }
}

__global__ void prep_W2(const float* __restrict__ Cre, const float* __restrict__ Cim) {
    int n = blockIdx.x;             // 0..1023
#pragma unroll
    for (int j = 0; j < 8; j++) {
        int k = threadIdx.x + j * 256;    // 0..2047
        float v = (k < 1024) ? Cre[n * 1024 + k] : -Cim[n * 1024 + (k - 1024)];
        g_W2[(size_t)n * 2048 + k] = tf32r(v);
    }
}

// ---------------- param prep ----------------
__global__ void prep_params(const float* __restrict__ nu_log,
                            const float* __restrict__ theta_log) {
    int h = blockIdx.x * blockDim.x + threadIdx.x;
    if (h >= H_DIM) return;
    float nu = expf(nu_log[h]);
    float th = expf(theta_log[h]);
    float mag = expf(-nu);
    float lre = mag * cosf(th);
    float lim = mag * sinf(th);
    g_lre[h] = lre; g_lim[h] = lim;
    float ar = 1.f, ai = 0.f;
    for (int t = 0; t < T_CHUNK; t++) {
        float nr = ar * lre - ai * lim;
        ai = ar * lim + ai * lre;
        ar = nr;
    }
    g_lTre[h] = ar; g_lTim[h] = ai;
}

// ---------------- scan (stacked [L x 2048]: re | im) ----------------
__global__ void scan_chunks() {
    int h = blockIdx.x * blockDim.x + threadIdx.x;
    int c = blockIdx.y;
    float lre = g_lre[h], lim = g_lim[h];
    float hr = 0.f, hi = 0.f;
#pragma unroll 4
    for (int t = 0; t < T_CHUNK; t++) {
        size_t row = (size_t)(c * T_CHUNK + t) * 2048;
        float br = g_Bu[row + h];
        float bi = g_Bu[row + 1024 + h];
        float nr = fmaf(lre, hr, fmaf(-lim, hi, br));
        float ni = fmaf(lre, hi, fmaf(lim, hr, bi));
        hr = nr; hi = ni;
    }
    g_Ere[c * H_DIM + h] = hr;
    g_Eim[c * H_DIM + h] = hi;
}

__global__ void scan_combine(float* __restrict__ out_head, int head_mode) {
    int h = blockIdx.x * blockDim.x + threadIdx.x;
    float lTre = g_lTre[h], lTim = g_lTim[h];
    float sr = 0.f, si = 0.f;
    for (int c = 0; c < N_CHUNK; c++) {
        g_Sre[c * H_DIM + h] = sr;
        g_Sim[c * H_DIM + h] = si;
        float er = g_Ere[c * H_DIM + h];
        float ei = g_Eim[c * H_DIM + h];
        float nr = fmaf(lTre, sr, fmaf(-lTim, si, er));
        float ni = fmaf(lTre, si, fmaf(lTim, sr, ei));
        sr = nr; si = ni;
    }
    if (head_mode == 1) {
        out_head[h] = sr;
    } else if (head_mode == 2) {
        out_head[2 * h]     = sr;
        out_head[2 * h + 1] = si;
    }
}

__global__ void scan_apply() {      // rewrites g_Bu in place with tf32-rounded hidden state
    int h = blockIdx.x * blockDim.x + threadIdx.x;
    int c = blockIdx.y;
    float lre = g_lre[h], lim = g_lim[h];
    float hr = g_Sre[c * H_DIM + h];
    float hi = g_Sim[c * H_DIM + h];
#pragma unroll 4
    for (int t = 0; t < T_CHUNK; t++) {
        size_t row = (size_t)(c * T_CHUNK + t) * 2048;
        float br = g_Bu[row + h];
        float bi = g_Bu[row + 1024 + h];
        float nr = fmaf(lre, hr, fmaf(-lim, hi, br));
        float ni = fmaf(lre, hi, fmaf(lim, hr, bi));
        hr = nr; hi = ni;
        g_Bu[row + h]        = tf32r(hr);
        g_Bu[row + 1024 + h] = tf32r(hi);
    }
}

// ---------------- launch ----------------
extern "C" void kernel_launch(void* const* d_in, const int* in_sizes, int n_in,
                              void* d_out, int out_size) {
    const float* x         = (const float*)d_in[0];
    const float* nu_log    = (const float*)d_in[1];
    const float* theta_log = (const float*)d_in[2];
    const float* gamma_log = (const float*)d_in[3];
    const float* Bre       = (const float*)d_in[4];
    const float* Bim       = (const float*)d_in[5];
    const float* Cre       = (const float*)d_in[6];
    const float* Cim       = (const float*)d_in[7];
    const float* Dp        = (const float*)d_in[8];

    float* out = (float*)d_out;
    long long head = (long long)out_size - (long long)L_SEQ * D_MOD;
    if (head < 0) head = 0;
    int head_mode = 0;
    if (head >= 2 * H_DIM)  head_mode = 2;
    else if (head >= H_DIM) head_mode = 1;
    float* out_head = out;
    float* out_y = out + head;

    float *pxr, *pW1, *pW2, *pBu;
    cudaGetSymbolAddress((void**)&pxr, g_xr);
    cudaGetSymbolAddress((void**)&pW1, g_W1);
    cudaGetSymbolAddress((void**)&pW2, g_W2);
    cudaGetSymbolAddress((void**)&pBu, g_Bu);

    cudaFuncSetAttribute(mma_gemm<0>, cudaFuncAttributeMaxDynamicSharedMemorySize, SMEM_TOTAL);
    cudaFuncSetAttribute(mma_gemm<1>, cudaFuncAttributeMaxDynamicSharedMemorySize, SMEM_TOTAL);

    prep_params<<<H_DIM / 256, 256>>>(nu_log, theta_log);
    conv_x<<<(L_SEQ * D_MOD) / (256 * 4), 256>>>(x);
    prep_W1<<<2 * H_DIM, 256>>>(Bre, Bim, gamma_log);
    prep_W2<<<D_MOD, 256>>>(Cre, Cim);

    // GEMM1: Bu[16384 x 2048] = x @ [B'_re ; B'_im]^T   (K=1024)
    mma_gemm<0><<<dim3(L_SEQ / 128, 2048 / 128), 256, SMEM_TOTAL>>>(
        pxr, pW1, pBu, 1024, 2048, nullptr, nullptr);

    scan_chunks<<<dim3(H_DIM / 256, N_CHUNK), 256>>>();
    scan_combine<<<H_DIM / 256, 256>>>(out_head, head_mode);
    scan_apply<<<dim3(H_DIM / 256, N_CHUNK), 256>>>();

    // GEMM2: y = [Hre|Him] @ [Cre|-Cim]^T + Dp*x   (K=2048)
    mma_gemm<1><<<dim3(L_SEQ / 128, 1024 / 128), 256, SMEM_TOTAL>>>(
        pBu, pW2, out_y, 2048, 1024, Dp, x);
}

// round 7
// speedup vs baseline: 1.3690x; 1.3690x over previous
#include <cuda_runtime.h>
#include <cuda_bf16.h>
#include <cstdint>

#define L_SEQ   16384
#define D_MOD   1024
#define H_DIM   1024
#define T_CHUNK 128
#define N_CHUNK 128   // L_SEQ / T_CHUNK

// ---------------- static scratch ----------------
__device__ float g_xr [(size_t)L_SEQ * D_MOD];          // tf32-rounded x
__device__ float g_W1 [(size_t)2 * H_DIM * D_MOD];      // [2048 x 1024] stacked re/im of scaled B (tf32)
__device__ float g_W2 [(size_t)D_MOD * 2 * H_DIM];      // [1024 x 2048] = [Cre | -Cim] (tf32)
__device__ float g_Bu [(size_t)L_SEQ * 2 * H_DIM];      // [16384 x 2048] Bu, then H (tf32) in place
__device__ float g_lre[H_DIM], g_lim[H_DIM];
__device__ float g_lTre[H_DIM], g_lTim[H_DIM];
__device__ float g_Ere[N_CHUNK * H_DIM], g_Eim[N_CHUNK * H_DIM];
__device__ float g_Sre[N_CHUNK * H_DIM], g_Sim[N_CHUNK * H_DIM];

// ---------------- helpers ----------------
__device__ __forceinline__ float tf32r(float x) {     // round-to-nearest tf32
    uint32_t u;
    asm("cvt.rna.tf32.f32 %0, %1;" : "=r"(u) : "f"(x));
    return __uint_as_float(u);
}
__device__ __forceinline__ void cp16(uint32_t dst, const void* src) {
    asm volatile("cp.async.cg.shared.global [%0], [%1], 16;" :: "r"(dst), "l"(src) : "memory");
}
__device__ __forceinline__ void cp_commit() { asm volatile("cp.async.commit_group;" ::: "memory"); }
__device__ __forceinline__ void cp_wait1()  { asm volatile("cp.async.wait_group 1;" ::: "memory"); }
__device__ __forceinline__ void cp_wait0()  { asm volatile("cp.async.wait_group 0;" ::: "memory"); }
__device__ __forceinline__ uint32_t smem_u32(const void* p) {
    uint32_t a;
    asm("{ .reg .u64 t; cvta.to.shared.u64 t, %1; cvt.u32.u64 %0, t; }" : "=r"(a) : "l"(p));
    return a;
}
__device__ __forceinline__ void mma_tf32(float* c, uint32_t a0, uint32_t a1, uint32_t a2, uint32_t a3,
                                         uint32_t b0, uint32_t b1) {
    asm volatile(
        "mma.sync.aligned.m16n8k8.row.col.f32.tf32.tf32.f32 "
        "{%0,%1,%2,%3}, {%4,%5,%6,%7}, {%8,%9}, {%0,%1,%2,%3};\n"
        : "+f"(c[0]), "+f"(c[1]), "+f"(c[2]), "+f"(c[3])
        : "r"(a0), "r"(a1), "r"(a2), "r"(a3), "r"(b0), "r"(b1));
}
// ldmatrix x4 of four 8x8-b16 tiles (= 8 rows x 4 f32 cols each); tf32 fragment
// mapping: lane l <- row l/4, f32 col l%4 — identical to the scalar loads it replaces
__device__ __forceinline__ void ldsm4(uint32_t* r, uint32_t addr) {
    asm volatile("ldmatrix.sync.aligned.m8n8.x4.shared.b16 {%0,%1,%2,%3}, [%4];"
                 : "=r"(r[0]), "=r"(r[1]), "=r"(r[2]), "=r"(r[3]) : "r"(addr));
}

// smem tile geometry: 128 rows x 32 cols, row stride 36 floats (conflict-free: 36 ≡ 4 mod 32)
#define TSTRIDE   36
#define TILE_FLTS (128 * TSTRIDE)            // 4608 floats = 18432 B
#define STAGE_FLTS (2 * TILE_FLTS)           // A tile + B tile
#define SMEM_TOTAL (2 * STAGE_FLTS * 4)      // double buffered = 73728 B

// ---------------- TF32 NT GEMM: O[m,n] = sum_k A[m,k] * W[n,k]  (+ EPI: Dp[n]*X[m,n]) ----------------
// 128x128 block tile, BK=32, 8 warps as 4(m) x 2(n); warp tile 32x64 -> mt=2, nt=8.  (R5 layout)
template <int EPI>
__global__ __launch_bounds__(256, 2) void mma_gemm(
    const float* __restrict__ A, const float* __restrict__ W,
    float* __restrict__ O, int K, int Nout,
    const float* __restrict__ Dp, const float* __restrict__ X)
{
    extern __shared__ float smem[];
    const uint32_t sbase = smem_u32(smem);
    const int tid = threadIdx.x;
    const int wid = tid >> 5, lane = tid & 31;
    const int g = lane >> 2, tig = lane & 3;
    const int wm = wid & 3, wn = wid >> 2;           // 4 x 2 warps; warp tile 32 x 64
    const int m0 = blockIdx.x * 128, n0 = blockIdx.y * 128;
    const int NC = K >> 5;                           // K chunks of 32

    const int r_ld  = tid >> 1;                      // 0..127 (row loaded by this thread)
    const int c4_ld = (tid & 1) * 4;                 // float4 index pairs: covers c4 0..7 with i-loop

    auto load_chunk = [&](int stage, int kc) {
        const uint32_t sa = sbase + (uint32_t)(stage * STAGE_FLTS) * 4u;
        const uint32_t sb = sa + (uint32_t)TILE_FLTS * 4u;
        const int kbase = kc * 32;
#pragma unroll
        for (int i = 0; i < 4; i++) {                // 4 float4 per thread per tile
            int c4 = c4_ld + (i & 3);                // 0..7
            uint32_t doff = (uint32_t)(r_ld * TSTRIDE + c4 * 4) * 4u;
            cp16(sa + doff, A + (size_t)(m0 + r_ld) * K + kbase + c4 * 4);
            cp16(sb + doff, W + (size_t)(n0 + r_ld) * K + kbase + c4 * 4);
        }
    };

    // per-lane ldmatrix base offset for B (bytes, within a stage):
    // LDSM q loads matrices {nt=2q cols0-3, nt=2q cols4-7, nt=2q+1 cols0-3, nt=2q+1 cols4-7}
    // lane-group lj = lane>>3 selects the matrix; lrow = lane&7 its row.
    const int lrow = lane & 7, lj = lane >> 3;
    const uint32_t b_lane = (uint32_t)(TILE_FLTS * 4
                                       + ((wn * 64 + (lj >> 1) * 8 + lrow) * TSTRIDE
                                          + (lj & 1) * 4) * 4);

    float acc[2][8][4];
#pragma unroll
    for (int mt = 0; mt < 2; mt++)
#pragma unroll
        for (int nt = 0; nt < 8; nt++)
#pragma unroll
            for (int q = 0; q < 4; q++) acc[mt][nt][q] = 0.f;

    load_chunk(0, 0);
    cp_commit();

    for (int kc = 0; kc < NC; kc++) {
        if (kc + 1 < NC) {
            load_chunk((kc + 1) & 1, kc + 1);
            cp_commit();
            cp_wait1();
        } else {
            cp_wait0();
        }
        __syncthreads();
        const float* As = smem + (kc & 1) * STAGE_FLTS;
        const uint32_t st = sbase + (uint32_t)((kc & 1) * STAGE_FLTS) * 4u;
#pragma unroll
        for (int s = 0; s < 4; s++) {
            const int k0 = s * 8;
            uint32_t af[2][4];
#pragma unroll
            for (int mt = 0; mt < 2; mt++) {
                int r = wm * 32 + mt * 16 + g;
                af[mt][0] = __float_as_uint(As[r * TSTRIDE + k0 + tig]);
                af[mt][1] = __float_as_uint(As[(r + 8) * TSTRIDE + k0 + tig]);
                af[mt][2] = __float_as_uint(As[r * TSTRIDE + k0 + tig + 4]);
                af[mt][3] = __float_as_uint(As[(r + 8) * TSTRIDE + k0 + tig + 4]);
            }
            uint32_t bf[8][2];
#pragma unroll
            for (int q = 0; q < 4; q++)
                ldsm4(&bf[q * 2][0],
                      st + b_lane + (uint32_t)(q * 16 * TSTRIDE * 4) + (uint32_t)(k0 * 4));
#pragma unroll
            for (int mt = 0; mt < 2; mt++)
#pragma unroll
                for (int nt = 0; nt < 8; nt++)
                    mma_tf32(acc[mt][nt], af[mt][0], af[mt][1], af[mt][2], af[mt][3],
                             bf[nt][0], bf[nt][1]);
        }
        __syncthreads();
    }

    // epilogue
#pragma unroll
    for (int mt = 0; mt < 2; mt++) {
        int row0 = m0 + wm * 32 + mt * 16 + g;
#pragma unroll
        for (int nt = 0; nt < 8; nt++) {
            int col = n0 + wn * 64 + nt * 8 + tig * 2;
            float2 v0 = make_float2(acc[mt][nt][0], acc[mt][nt][1]);
            float2 v1 = make_float2(acc[mt][nt][2], acc[mt][nt][3]);
            if (EPI) {
                float2 dp = *(const float2*)(Dp + col);
                float2 x0 = *(const float2*)(X + (size_t)row0 * 1024 + col);
                float2 x1 = *(const float2*)(X + (size_t)(row0 + 8) * 1024 + col);
                v0.x += dp.x * x0.x; v0.y += dp.y * x0.y;
                v1.x += dp.x * x1.x; v1.y += dp.y * x1.y;
            }
            *(float2*)(O + (size_t)row0 * Nout + col) = v0;
            *(float2*)(O + (size_t)(row0 + 8) * Nout + col) = v1;
        }
    }
}

// ---------------- conversions (tf32 pre-rounding) ----------------
__global__ void conv_x(const float* __restrict__ x) {
    size_t i = (size_t)(blockIdx.x * blockDim.x + threadIdx.x) * 4;
    float4 v = *(const float4*)(x + i);
    v.x = tf32r(v.x); v.y = tf32r(v.y); v.z = tf32r(v.z); v.w = tf32r(v.w);
    *(float4*)(g_xr + i) = v;
}

__global__ void prep_W1(const float* __restrict__ Bre, const float* __restrict__ Bim,
                        const float* __restrict__ gamma_log) {
    int n = blockIdx.x;             // 0..2047
    int h = n & 1023;
    const float* src = (n < 1024) ? Bre : Bim;
    float eg = expf(gamma_log[h]);
#pragma unroll
    for (int j = 0; j < 4; j++) {
        int k = threadIdx.x * 4 + j;
        g_W1[(size_t)n * 1024 + k] = tf32r(src[h * 1024 + k] * eg);
    }
}

__global__ void prep_W2(const float* __restrict__ Cre, const float* __restrict__ Cim) {
    int n = blockIdx.x;             // 0..1023
#pragma unroll
    for (int j = 0; j < 8; j++) {
        int k = threadIdx.x + j * 256;    // 0..2047
        float v = (k < 1024) ? Cre[n * 1024 + k] : -Cim[n * 1024 + (k - 1024)];
        g_W2[(size_t)n * 2048 + k] = tf32r(v);
    }
}

// ---------------- param prep ----------------
__global__ void prep_params(const float* __restrict__ nu_log,
                            const float* __restrict__ theta_log) {
    int h = blockIdx.x * blockDim.x + threadIdx.x;
    if (h >= H_DIM) return;
    float nu = expf(nu_log[h]);
    float th = expf(theta_log[h]);
    float mag = expf(-nu);
    float lre = mag * cosf(th);
    float lim = mag * sinf(th);
    g_lre[h] = lre; g_lim[h] = lim;
    float ar = 1.f, ai = 0.f;
    for (int t = 0; t < T_CHUNK; t++) {
        float nr = ar * lre - ai * lim;
        ai = ar * lim + ai * lre;
        ar = nr;
    }
    g_lTre[h] = ar; g_lTim[h] = ai;
}

// ---------------- scan (stacked [L x 2048]: re | im) ----------------
__global__ void scan_chunks() {
    int h = blockIdx.x * blockDim.x + threadIdx.x;
    int c = blockIdx.y;
    float lre = g_lre[h], lim = g_lim[h];
    float hr = 0.f, hi = 0.f;
#pragma unroll 4
    for (int t = 0; t < T_CHUNK; t++) {
        size_t row = (size_t)(c * T_CHUNK + t) * 2048;
        float br = g_Bu[row + h];
        float bi = g_Bu[row + 1024 + h];
        float nr = fmaf(lre, hr, fmaf(-lim, hi, br));
        float ni = fmaf(lre, hi, fmaf(lim, hr, bi));
        hr = nr; hi = ni;
    }
    g_Ere[c * H_DIM + h] = hr;
    g_Eim[c * H_DIM + h] = hi;
}

__global__ void scan_combine(float* __restrict__ out_head, int head_mode) {
    int h = blockIdx.x * blockDim.x + threadIdx.x;
    float lTre = g_lTre[h], lTim = g_lTim[h];
    float sr = 0.f, si = 0.f;
    for (int c = 0; c < N_CHUNK; c++) {
        g_Sre[c * H_DIM + h] = sr;
        g_Sim[c * H_DIM + h] = si;
        float er = g_Ere[c * H_DIM + h];
        float ei = g_Eim[c * H_DIM + h];
        float nr = fmaf(lTre, sr, fmaf(-lTim, si, er));
        float ni = fmaf(lTre, si, fmaf(lTim, sr, ei));
        sr = nr; si = ni;
    }
    if (head_mode == 1) {
        out_head[h] = sr;
    } else if (head_mode == 2) {
        out_head[2 * h]     = sr;
        out_head[2 * h + 1] = si;
    }
}

__global__ void scan_apply() {      // rewrites g_Bu in place with tf32-rounded hidden state
    int h = blockIdx.x * blockDim.x + threadIdx.x;
    int c = blockIdx.y;
    float lre = g_lre[h], lim = g_lim[h];
    float hr = g_Sre[c * H_DIM + h];
    float hi = g_Sim[c * H_DIM + h];
#pragma unroll 4
    for (int t = 0; t < T_CHUNK; t++) {
        size_t row = (size_t)(c * T_CHUNK + t) * 2048;
        float br = g_Bu[row + h];
        float bi = g_Bu[row + 1024 + h];
        float nr = fmaf(lre, hr, fmaf(-lim, hi, br));
        float ni = fmaf(lre, hi, fmaf(lim, hr, bi));
        hr = nr; hi = ni;
        g_Bu[row + h]        = tf32r(hr);
        g_Bu[row + 1024 + h] = tf32r(hi);
    }
}

// ---------------- launch ----------------
extern "C" void kernel_launch(void* const* d_in, const int* in_sizes, int n_in,
                              void* d_out, int out_size) {
    const float* x         = (const float*)d_in[0];
    const float* nu_log    = (const float*)d_in[1];
    const float* theta_log = (const float*)d_in[2];
    const float* gamma_log = (const float*)d_in[3];
    const float* Bre       = (const float*)d_in[4];
    const float* Bim       = (const float*)d_in[5];
    const float* Cre       = (const float*)d_in[6];
    const float* Cim       = (const float*)d_in[7];
    const float* Dp        = (const float*)d_in[8];

    float* out = (float*)d_out;
    long long head = (long long)out_size - (long long)L_SEQ * D_MOD;
    if (head < 0) head = 0;
    int head_mode = 0;
    if (head >= 2 * H_DIM)  head_mode = 2;
    else if (head >= H_DIM) head_mode = 1;
    float* out_head = out;
    float* out_y = out + head;

    float *pxr, *pW1, *pW2, *pBu;
    cudaGetSymbolAddress((void**)&pxr, g_xr);
    cudaGetSymbolAddress((void**)&pW1, g_W1);
    cudaGetSymbolAddress((void**)&pW2, g_W2);
    cudaGetSymbolAddress((void**)&pBu, g_Bu);

    cudaFuncSetAttribute(mma_gemm<0>, cudaFuncAttributeMaxDynamicSharedMemorySize, SMEM_TOTAL);
    cudaFuncSetAttribute(mma_gemm<1>, cudaFuncAttributeMaxDynamicSharedMemorySize, SMEM_TOTAL);

    prep_params<<<H_DIM / 256, 256>>>(nu_log, theta_log);
    conv_x<<<(L_SEQ * D_MOD) / (256 * 4), 256>>>(x);
    prep_W1<<<2 * H_DIM, 256>>>(Bre, Bim, gamma_log);
    prep_W2<<<D_MOD, 256>>>(Cre, Cim);

    // GEMM1: Bu[16384 x 2048] = x @ [B'_re ; B'_im]^T   (K=1024)
    mma_gemm<0><<<dim3(L_SEQ / 128, 2048 / 128), 256, SMEM_TOTAL>>>(
        pxr, pW1, pBu, 1024, 2048, nullptr, nullptr);

    scan_chunks<<<dim3(H_DIM / 256, N_CHUNK), 256>>>();
    scan_combine<<<H_DIM / 256, 256>>>(out_head, head_mode);
    scan_apply<<<dim3(H_DIM / 256, N_CHUNK), 256>>>();

    // GEMM2: y = [Hre|Him] @ [Cre|-Cim]^T + Dp*x   (K=2048)
    mma_gemm<1><<<dim3(L_SEQ / 128, 1024 / 128), 256, SMEM_TOTAL>>>(
        pBu, pW2, out_y, 2048, 1024, Dp, x);
}

// round 8
// speedup vs baseline: 2.3614x; 1.7250x over previous
#include <cuda_runtime.h>
#include <cuda_fp16.h>
#include <cstdint>

#define L_SEQ   16384
#define D_MOD   1024
#define H_DIM   1024
#define T_CHUNK 128
#define N_CHUNK 128   // L_SEQ / T_CHUNK

// ---------------- static scratch ----------------
__device__ __half g_xh [(size_t)L_SEQ * D_MOD];          // fp16 x
__device__ __half g_W1h[(size_t)2 * H_DIM * D_MOD];      // [2048 x 1024] stacked re/im of scaled B
__device__ __half g_W2h[(size_t)D_MOD * 2 * H_DIM];      // [1024 x 2048] = [Cre | -Cim]
__device__ float  g_Bu [(size_t)L_SEQ * 2 * H_DIM];      // [16384 x 2048] Bu (fp32, scan input)
__device__ __half g_Hh [(size_t)L_SEQ * 2 * H_DIM];      // [16384 x 2048] hidden re|im (fp16)
__device__ float g_lre[H_DIM], g_lim[H_DIM];
__device__ float g_lTre[H_DIM], g_lTim[H_DIM];
__device__ float g_Ere[N_CHUNK * H_DIM], g_Eim[N_CHUNK * H_DIM];
__device__ float g_Sre[N_CHUNK * H_DIM], g_Sim[N_CHUNK * H_DIM];

// ---------------- helpers ----------------
__device__ __forceinline__ void cp16(uint32_t dst, const void* src) {
    asm volatile("cp.async.cg.shared.global [%0], [%1], 16;" :: "r"(dst), "l"(src) : "memory");
}
__device__ __forceinline__ void cp_commit() { asm volatile("cp.async.commit_group;" ::: "memory"); }
__device__ __forceinline__ void cp_wait1()  { asm volatile("cp.async.wait_group 1;" ::: "memory"); }
__device__ __forceinline__ void cp_wait0()  { asm volatile("cp.async.wait_group 0;" ::: "memory"); }
__device__ __forceinline__ uint32_t smem_u32(const void* p) {
    uint32_t a;
    asm("{ .reg .u64 t; cvta.to.shared.u64 t, %1; cvt.u32.u64 %0, t; }" : "=r"(a) : "l"(p));
    return a;
}
// fp16 HMMA, fp32 accumulate: 4 A regs (8 halves), 2 B regs (4 halves)
__device__ __forceinline__ void mma_f16(float* c, uint32_t a0, uint32_t a1, uint32_t a2, uint32_t a3,
                                        uint32_t b0, uint32_t b1) {
    asm volatile(
        "mma.sync.aligned.m16n8k16.row.col.f32.f16.f16.f32 "
        "{%0,%1,%2,%3}, {%4,%5,%6,%7}, {%8,%9}, {%0,%1,%2,%3};\n"
        : "+f"(c[0]), "+f"(c[1]), "+f"(c[2]), "+f"(c[3])
        : "r"(a0), "r"(a1), "r"(a2), "r"(a3), "r"(b0), "r"(b1));
}

// smem tile: 128 rows x 64 halves (= 32 b32), row stride 36 b32 (conflict-free: 36 ≡ 4 mod 32)
#define TSTRIDE   36                         // in b32 units
#define TILE_U32  (128 * TSTRIDE)            // 4608 b32 = 18432 B
#define STAGE_U32 (2 * TILE_U32)             // A tile + B tile
#define SMEM_TOTAL (2 * STAGE_U32 * 4)       // double buffered = 73728 B

// ---------------- FP16 NT GEMM: O[m,n] = sum_k A[m,k] * W[n,k]  (+ EPI: Dp[n]*X[m,n]) ----------------
// 128x128 block tile, BK=64 halves, 8 warps as 4(m) x 2(n); warp tile 32x64 -> mt=2, nt=8. (R5 layout)
// K, offsets in HALF units.
template <int EPI>
__global__ __launch_bounds__(256, 2) void mma_gemm(
    const __half* __restrict__ A, const __half* __restrict__ W,
    float* __restrict__ O, int K, int Nout,
    const float* __restrict__ Dp, const float* __restrict__ X)
{
    extern __shared__ uint32_t smem[];
    const uint32_t sbase = smem_u32(smem);
    const int tid = threadIdx.x;
    const int wid = tid >> 5, lane = tid & 31;
    const int g = lane >> 2, tig = lane & 3;
    const int wm = wid & 3, wn = wid >> 2;           // 4 x 2 warps; warp tile 32 x 64
    const int m0 = blockIdx.x * 128, n0 = blockIdx.y * 128;
    const int NC = K >> 6;                           // K chunks of 64 halves

    const int r_ld  = tid >> 1;                      // 0..127 (row loaded by this thread)
    const int c4_ld = (tid & 1) * 4;                 // 16B-chunk index base (8 chunks per 128B row)

    auto load_chunk = [&](int stage, int kc) {
        const uint32_t sa = sbase + (uint32_t)(stage * STAGE_U32) * 4u;
        const uint32_t sb = sa + (uint32_t)TILE_U32 * 4u;
        const int kbase = kc * 64;                   // halves
#pragma unroll
        for (int i = 0; i < 4; i++) {
            int c4 = c4_ld + (i & 3);                // 0..7 (16B chunks)
            uint32_t doff = (uint32_t)(r_ld * TSTRIDE + c4 * 4) * 4u;
            cp16(sa + doff, A + (size_t)(m0 + r_ld) * K + kbase + c4 * 8);
            cp16(sb + doff, W + (size_t)(n0 + r_ld) * K + kbase + c4 * 8);
        }
    };

    float acc[2][8][4];
#pragma unroll
    for (int mt = 0; mt < 2; mt++)
#pragma unroll
        for (int nt = 0; nt < 8; nt++)
#pragma unroll
            for (int q = 0; q < 4; q++) acc[mt][nt][q] = 0.f;

    load_chunk(0, 0);
    cp_commit();

    for (int kc = 0; kc < NC; kc++) {
        if (kc + 1 < NC) {
            load_chunk((kc + 1) & 1, kc + 1);
            cp_commit();
            cp_wait1();
        } else {
            cp_wait0();
        }
        __syncthreads();
        const uint32_t* As = smem + (kc & 1) * STAGE_U32;
        const uint32_t* Bs = As + TILE_U32;
#pragma unroll
        for (int s = 0; s < 4; s++) {                // 4 k16-steps; each = 8 b32
            const int k0 = s * 8;                    // b32 units
            uint32_t af[2][4];
#pragma unroll
            for (int mt = 0; mt < 2; mt++) {
                int r = wm * 32 + mt * 16 + g;
                af[mt][0] = As[r * TSTRIDE + k0 + tig];
                af[mt][1] = As[(r + 8) * TSTRIDE + k0 + tig];
                af[mt][2] = As[r * TSTRIDE + k0 + tig + 4];
                af[mt][3] = As[(r + 8) * TSTRIDE + k0 + tig + 4];
            }
            uint32_t bf[8][2];
#pragma unroll
            for (int nt = 0; nt < 8; nt++) {
                int n = wn * 64 + nt * 8 + g;
                bf[nt][0] = Bs[n * TSTRIDE + k0 + tig];
                bf[nt][1] = Bs[n * TSTRIDE + k0 + tig + 4];
            }
#pragma unroll
            for (int mt = 0; mt < 2; mt++)
#pragma unroll
                for (int nt = 0; nt < 8; nt++)
                    mma_f16(acc[mt][nt], af[mt][0], af[mt][1], af[mt][2], af[mt][3],
                            bf[nt][0], bf[nt][1]);
        }
        __syncthreads();
    }

    // epilogue
#pragma unroll
    for (int mt = 0; mt < 2; mt++) {
        int row0 = m0 + wm * 32 + mt * 16 + g;
#pragma unroll
        for (int nt = 0; nt < 8; nt++) {
            int col = n0 + wn * 64 + nt * 8 + tig * 2;
            float2 v0 = make_float2(acc[mt][nt][0], acc[mt][nt][1]);
            float2 v1 = make_float2(acc[mt][nt][2], acc[mt][nt][3]);
            if (EPI) {
                float2 dp = *(const float2*)(Dp + col);
                float2 x0 = *(const float2*)(X + (size_t)row0 * 1024 + col);
                float2 x1 = *(const float2*)(X + (size_t)(row0 + 8) * 1024 + col);
                v0.x += dp.x * x0.x; v0.y += dp.y * x0.y;
                v1.x += dp.x * x1.x; v1.y += dp.y * x1.y;
            }
            *(float2*)(O + (size_t)row0 * Nout + col) = v0;
            *(float2*)(O + (size_t)(row0 + 8) * Nout + col) = v1;
        }
    }
}

// ---------------- conversions (fp16 pre-rounding) ----------------
__global__ void conv_x(const float* __restrict__ x) {
    size_t i = (size_t)(blockIdx.x * blockDim.x + threadIdx.x) * 4;
    float4 v = *(const float4*)(x + i);
    g_xh[i + 0] = __float2half_rn(v.x);
    g_xh[i + 1] = __float2half_rn(v.y);
    g_xh[i + 2] = __float2half_rn(v.z);
    g_xh[i + 3] = __float2half_rn(v.w);
}

__global__ void prep_W1(const float* __restrict__ Bre, const float* __restrict__ Bim,
                        const float* __restrict__ gamma_log) {
    int n = blockIdx.x;             // 0..2047
    int h = n & 1023;
    const float* src = (n < 1024) ? Bre : Bim;
    float eg = expf(gamma_log[h]);
#pragma unroll
    for (int j = 0; j < 4; j++) {
        int k = threadIdx.x * 4 + j;
        g_W1h[(size_t)n * 1024 + k] = __float2half_rn(src[h * 1024 + k] * eg);
    }
}

__global__ void prep_W2(const float* __restrict__ Cre, const float* __restrict__ Cim) {
    int n = blockIdx.x;             // 0..1023
#pragma unroll
    for (int j = 0; j < 8; j++) {
        int k = threadIdx.x + j * 256;    // 0..2047
        float v = (k < 1024) ? Cre[n * 1024 + k] : -Cim[n * 1024 + (k - 1024)];
        g_W2h[(size_t)n * 2048 + k] = __float2half_rn(v);
    }
}

// ---------------- param prep ----------------
__global__ void prep_params(const float* __restrict__ nu_log,
                            const float* __restrict__ theta_log) {
    int h = blockIdx.x * blockDim.x + threadIdx.x;
    if (h >= H_DIM) return;
    float nu = expf(nu_log[h]);
    float th = expf(theta_log[h]);
    float mag = expf(-nu);
    float lre = mag * cosf(th);
    float lim = mag * sinf(th);
    g_lre[h] = lre; g_lim[h] = lim;
    float ar = 1.f, ai = 0.f;
    for (int t = 0; t < T_CHUNK; t++) {
        float nr = ar * lre - ai * lim;
        ai = ar * lim + ai * lre;
        ar = nr;
    }
    g_lTre[h] = ar; g_lTim[h] = ai;
}

// ---------------- scan (stacked [L x 2048]: re | im) ----------------
__global__ void scan_chunks() {
    int h = blockIdx.x * blockDim.x + threadIdx.x;
    int c = blockIdx.y;
    float lre = g_lre[h], lim = g_lim[h];
    float hr = 0.f, hi = 0.f;
#pragma unroll 4
    for (int t = 0; t < T_CHUNK; t++) {
        size_t row = (size_t)(c * T_CHUNK + t) * 2048;
        float br = g_Bu[row + h];
        float bi = g_Bu[row + 1024 + h];
        float nr = fmaf(lre, hr, fmaf(-lim, hi, br));
        float ni = fmaf(lre, hi, fmaf(lim, hr, bi));
        hr = nr; hi = ni;
    }
    g_Ere[c * H_DIM + h] = hr;
    g_Eim[c * H_DIM + h] = hi;
}

__global__ void scan_combine(float* __restrict__ out_head, int head_mode) {
    int h = blockIdx.x * blockDim.x + threadIdx.x;
    float lTre = g_lTre[h], lTim = g_lTim[h];
    float sr = 0.f, si = 0.f;
    for (int c = 0; c < N_CHUNK; c++) {
        g_Sre[c * H_DIM + h] = sr;
        g_Sim[c * H_DIM + h] = si;
        float er = g_Ere[c * H_DIM + h];
        float ei = g_Eim[c * H_DIM + h];
        float nr = fmaf(lTre, sr, fmaf(-lTim, si, er));
        float ni = fmaf(lTre, si, fmaf(lTim, sr, ei));
        sr = nr; si = ni;
    }
    if (head_mode == 1) {
        out_head[h] = sr;
    } else if (head_mode == 2) {
        out_head[2 * h]     = sr;
        out_head[2 * h + 1] = si;
    }
}

__global__ void scan_apply() {      // emits fp16 hidden state into g_Hh
    int h = blockIdx.x * blockDim.x + threadIdx.x;
    int c = blockIdx.y;
    float lre = g_lre[h], lim = g_lim[h];
    float hr = g_Sre[c * H_DIM + h];
    float hi = g_Sim[c * H_DIM + h];
#pragma unroll 4
    for (int t = 0; t < T_CHUNK; t++) {
        size_t row = (size_t)(c * T_CHUNK + t) * 2048;
        float br = g_Bu[row + h];
        float bi = g_Bu[row + 1024 + h];
        float nr = fmaf(lre, hr, fmaf(-lim, hi, br));
        float ni = fmaf(lre, hi, fmaf(lim, hr, bi));
        hr = nr; hi = ni;
        g_Hh[row + h]        = __float2half_rn(hr);
        g_Hh[row + 1024 + h] = __float2half_rn(hi);
    }
}

// ---------------- launch ----------------
extern "C" void kernel_launch(void* const* d_in, const int* in_sizes, int n_in,
                              void* d_out, int out_size) {
    const float* x         = (const float*)d_in[0];
    const float* nu_log    = (const float*)d_in[1];
    const float* theta_log = (const float*)d_in[2];
    const float* gamma_log = (const float*)d_in[3];
    const float* Bre       = (const float*)d_in[4];
    const float* Bim       = (const float*)d_in[5];
    const float* Cre       = (const float*)d_in[6];
    const float* Cim       = (const float*)d_in[7];
    const float* Dp        = (const float*)d_in[8];

    float* out = (float*)d_out;
    long long head = (long long)out_size - (long long)L_SEQ * D_MOD;
    if (head < 0) head = 0;
    int head_mode = 0;
    if (head >= 2 * H_DIM)  head_mode = 2;
    else if (head >= H_DIM) head_mode = 1;
    float* out_head = out;
    float* out_y = out + head;

    __half *pxh, *pW1h, *pW2h, *pHh;
    float *pBu;
    cudaGetSymbolAddress((void**)&pxh,  g_xh);
    cudaGetSymbolAddress((void**)&pW1h, g_W1h);
    cudaGetSymbolAddress((void**)&pW2h, g_W2h);
    cudaGetSymbolAddress((void**)&pHh,  g_Hh);
    cudaGetSymbolAddress((void**)&pBu,  g_Bu);

    cudaFuncSetAttribute(mma_gemm<0>, cudaFuncAttributeMaxDynamicSharedMemorySize, SMEM_TOTAL);
    cudaFuncSetAttribute(mma_gemm<1>, cudaFuncAttributeMaxDynamicSharedMemorySize, SMEM_TOTAL);

    prep_params<<<H_DIM / 256, 256>>>(nu_log, theta_log);
    conv_x<<<(L_SEQ * D_MOD) / (256 * 4), 256>>>(x);
    prep_W1<<<2 * H_DIM, 256>>>(Bre, Bim, gamma_log);
    prep_W2<<<D_MOD, 256>>>(Cre, Cim);

    // GEMM1: Bu[16384 x 2048] = x @ [B'_re ; B'_im]^T   (K=1024 halves)
    mma_gemm<0><<<dim3(L_SEQ / 128, 2048 / 128), 256, SMEM_TOTAL>>>(
        pxh, pW1h, pBu, 1024, 2048, nullptr, nullptr);

    scan_chunks<<<dim3(H_DIM / 256, N_CHUNK), 256>>>();
    scan_combine<<<H_DIM / 256, 256>>>(out_head, head_mode);
    scan_apply<<<dim3(H_DIM / 256, N_CHUNK), 256>>>();

    // GEMM2: y = [Hre|Him] @ [Cre|-Cim]^T + Dp*x   (K=2048 halves)
    mma_gemm<1><<<dim3(L_SEQ / 128, 1024 / 128), 256, SMEM_TOTAL>>>(
        pHh, pW2h, out_y, 2048, 1024, Dp, x);
}

// round 9
// speedup vs baseline: 2.4190x; 1.0244x over previous
#include <cuda_runtime.h>
#include <cuda_fp16.h>
#include <cstdint>

#define L_SEQ   16384
#define D_MOD   1024
#define H_DIM   1024
#define T_CHUNK 128
#define N_CHUNK 128   // L_SEQ / T_CHUNK

// ---------------- static scratch ----------------
__device__ __half g_xh [(size_t)L_SEQ * D_MOD];          // fp16 x
__device__ __half g_W1h[(size_t)2 * H_DIM * D_MOD];      // [2048 x 1024] stacked re/im of scaled B
__device__ __half g_W2h[(size_t)D_MOD * 2 * H_DIM];      // [1024 x 2048] = [Cre | -Cim]
__device__ __half g_Buh[(size_t)L_SEQ * 2 * H_DIM];      // [16384 x 2048] Bu fp16 (scan input)
__device__ __half g_Hh [(size_t)L_SEQ * 2 * H_DIM];      // [16384 x 2048] hidden re|im (fp16)
__device__ float g_lre[H_DIM], g_lim[H_DIM];
__device__ float g_lTre[H_DIM], g_lTim[H_DIM];
__device__ float g_Ere[N_CHUNK * H_DIM], g_Eim[N_CHUNK * H_DIM];
__device__ float g_Sre[N_CHUNK * H_DIM], g_Sim[N_CHUNK * H_DIM];

// ---------------- helpers ----------------
__device__ __forceinline__ void cp16(uint32_t dst, const void* src) {
    asm volatile("cp.async.cg.shared.global [%0], [%1], 16;" :: "r"(dst), "l"(src) : "memory");
}
__device__ __forceinline__ void cp_commit() { asm volatile("cp.async.commit_group;" ::: "memory"); }
__device__ __forceinline__ void cp_wait1()  { asm volatile("cp.async.wait_group 1;" ::: "memory"); }
__device__ __forceinline__ void cp_wait0()  { asm volatile("cp.async.wait_group 0;" ::: "memory"); }
__device__ __forceinline__ uint32_t smem_u32(const void* p) {
    uint32_t a;
    asm("{ .reg .u64 t; cvta.to.shared.u64 t, %1; cvt.u32.u64 %0, t; }" : "=r"(a) : "l"(p));
    return a;
}
// fp16 HMMA, fp32 accumulate: 4 A regs (8 halves), 2 B regs (4 halves)
__device__ __forceinline__ void mma_f16(float* c, uint32_t a0, uint32_t a1, uint32_t a2, uint32_t a3,
                                        uint32_t b0, uint32_t b1) {
    asm volatile(
        "mma.sync.aligned.m16n8k16.row.col.f32.f16.f16.f32 "
        "{%0,%1,%2,%3}, {%4,%5,%6,%7}, {%8,%9}, {%0,%1,%2,%3};\n"
        : "+f"(c[0]), "+f"(c[1]), "+f"(c[2]), "+f"(c[3])
        : "r"(a0), "r"(a1), "r"(a2), "r"(a3), "r"(b0), "r"(b1));
}

// smem tile: 128 rows x 64 halves (= 32 b32), row stride 36 b32 (conflict-free: 36 ≡ 4 mod 32)
#define TSTRIDE   36                         // in b32 units
#define TILE_U32  (128 * TSTRIDE)            // 4608 b32 = 18432 B
#define STAGE_U32 (2 * TILE_U32)             // A tile + B tile
#define SMEM_TOTAL (2 * STAGE_U32 * 4)       // double buffered = 73728 B

// ---------------- FP16 NT GEMM: O[m,n] = sum_k A[m,k] * W[n,k]  (+ EPI: Dp[n]*X[m,n]) ----------------
// 128x128 block tile, BK=64 halves, 8 warps as 4(m) x 2(n); warp tile 32x64 -> mt=2, nt=8.
// K, offsets in HALF units.  OUTH=1: store __half2 into a half buffer; else float2.
template <int EPI, int OUTH>
__global__ __launch_bounds__(256, 2) void mma_gemm(
    const __half* __restrict__ A, const __half* __restrict__ W,
    void* __restrict__ O, int K, int Nout,
    const float* __restrict__ Dp, const float* __restrict__ X)
{
    extern __shared__ uint32_t smem[];
    const uint32_t sbase = smem_u32(smem);
    const int tid = threadIdx.x;
    const int wid = tid >> 5, lane = tid & 31;
    const int g = lane >> 2, tig = lane & 3;
    const int wm = wid & 3, wn = wid >> 2;           // 4 x 2 warps; warp tile 32 x 64
    const int m0 = blockIdx.x * 128, n0 = blockIdx.y * 128;
    const int NC = K >> 6;                           // K chunks of 64 halves

    const int r_ld  = tid >> 1;                      // 0..127 (row loaded by this thread)
    const int c4_ld = (tid & 1) * 4;                 // 16B-chunk index base (8 chunks per 128B row)

    auto load_chunk = [&](int stage, int kc) {
        const uint32_t sa = sbase + (uint32_t)(stage * STAGE_U32) * 4u;
        const uint32_t sb = sa + (uint32_t)TILE_U32 * 4u;
        const int kbase = kc * 64;                   // halves
#pragma unroll
        for (int i = 0; i < 4; i++) {
            int c4 = c4_ld + (i & 3);                // 0..7 (16B chunks)
            uint32_t doff = (uint32_t)(r_ld * TSTRIDE + c4 * 4) * 4u;
            cp16(sa + doff, A + (size_t)(m0 + r_ld) * K + kbase + c4 * 8);
            cp16(sb + doff, W + (size_t)(n0 + r_ld) * K + kbase + c4 * 8);
        }
    };

    float acc[2][8][4];
#pragma unroll
    for (int mt = 0; mt < 2; mt++)
#pragma unroll
        for (int nt = 0; nt < 8; nt++)
#pragma unroll
            for (int q = 0; q < 4; q++) acc[mt][nt][q] = 0.f;

    load_chunk(0, 0);
    cp_commit();

    for (int kc = 0; kc < NC; kc++) {
        if (kc + 1 < NC) {
            load_chunk((kc + 1) & 1, kc + 1);
            cp_commit();
            cp_wait1();
        } else {
            cp_wait0();
        }
        __syncthreads();
        const uint32_t* As = smem + (kc & 1) * STAGE_U32;
        const uint32_t* Bs = As + TILE_U32;
#pragma unroll
        for (int s = 0; s < 4; s++) {                // 4 k16-steps; each = 8 b32
            const int k0 = s * 8;                    // b32 units
            uint32_t af[2][4];
#pragma unroll
            for (int mt = 0; mt < 2; mt++) {
                int r = wm * 32 + mt * 16 + g;
                af[mt][0] = As[r * TSTRIDE + k0 + tig];
                af[mt][1] = As[(r + 8) * TSTRIDE + k0 + tig];
                af[mt][2] = As[r * TSTRIDE + k0 + tig + 4];
                af[mt][3] = As[(r + 8) * TSTRIDE + k0 + tig + 4];
            }
            uint32_t bf[8][2];
#pragma unroll
            for (int nt = 0; nt < 8; nt++) {
                int n = wn * 64 + nt * 8 + g;
                bf[nt][0] = Bs[n * TSTRIDE + k0 + tig];
                bf[nt][1] = Bs[n * TSTRIDE + k0 + tig + 4];
            }
#pragma unroll
            for (int mt = 0; mt < 2; mt++)
#pragma unroll
                for (int nt = 0; nt < 8; nt++)
                    mma_f16(acc[mt][nt], af[mt][0], af[mt][1], af[mt][2], af[mt][3],
                            bf[nt][0], bf[nt][1]);
        }
        __syncthreads();
    }

    // epilogue
#pragma unroll
    for (int mt = 0; mt < 2; mt++) {
        int row0 = m0 + wm * 32 + mt * 16 + g;
#pragma unroll
        for (int nt = 0; nt < 8; nt++) {
            int col = n0 + wn * 64 + nt * 8 + tig * 2;
            float2 v0 = make_float2(acc[mt][nt][0], acc[mt][nt][1]);
            float2 v1 = make_float2(acc[mt][nt][2], acc[mt][nt][3]);
            if (EPI) {
                float2 dp = *(const float2*)(Dp + col);
                float2 x0 = *(const float2*)(X + (size_t)row0 * 1024 + col);
                float2 x1 = *(const float2*)(X + (size_t)(row0 + 8) * 1024 + col);
                v0.x += dp.x * x0.x; v0.y += dp.y * x0.y;
                v1.x += dp.x * x1.x; v1.y += dp.y * x1.y;
            }
            if (OUTH) {
                __half* Oh = (__half*)O;
                *(__half2*)(Oh + (size_t)row0 * Nout + col) = __floats2half2_rn(v0.x, v0.y);
                *(__half2*)(Oh + (size_t)(row0 + 8) * Nout + col) = __floats2half2_rn(v1.x, v1.y);
            } else {
                float* Of = (float*)O;
                *(float2*)(Of + (size_t)row0 * Nout + col) = v0;
                *(float2*)(Of + (size_t)(row0 + 8) * Nout + col) = v1;
            }
        }
    }
}

// ---------------- conversions (fp16 pre-rounding) ----------------
__global__ void conv_x(const float* __restrict__ x) {
    size_t i = (size_t)(blockIdx.x * blockDim.x + threadIdx.x) * 4;
    float4 v = *(const float4*)(x + i);
    g_xh[i + 0] = __float2half_rn(v.x);
    g_xh[i + 1] = __float2half_rn(v.y);
    g_xh[i + 2] = __float2half_rn(v.z);
    g_xh[i + 3] = __float2half_rn(v.w);
}

__global__ void prep_W1(const float* __restrict__ Bre, const float* __restrict__ Bim,
                        const float* __restrict__ gamma_log) {
    int n = blockIdx.x;             // 0..2047
    int h = n & 1023;
    const float* src = (n < 1024) ? Bre : Bim;
    float eg = expf(gamma_log[h]);
#pragma unroll
    for (int j = 0; j < 4; j++) {
        int k = threadIdx.x * 4 + j;
        g_W1h[(size_t)n * 1024 + k] = __float2half_rn(src[h * 1024 + k] * eg);
    }
}

__global__ void prep_W2(const float* __restrict__ Cre, const float* __restrict__ Cim) {
    int n = blockIdx.x;             // 0..1023
#pragma unroll
    for (int j = 0; j < 8; j++) {
        int k = threadIdx.x + j * 256;    // 0..2047
        float v = (k < 1024) ? Cre[n * 1024 + k] : -Cim[n * 1024 + (k - 1024)];
        g_W2h[(size_t)n * 2048 + k] = __float2half_rn(v);
    }
}

// ---------------- param prep ----------------
__global__ void prep_params(const float* __restrict__ nu_log,
                            const float* __restrict__ theta_log) {
    int h = blockIdx.x * blockDim.x + threadIdx.x;
    if (h >= H_DIM) return;
    float nu = expf(nu_log[h]);
    float th = expf(theta_log[h]);
    float mag = expf(-nu);
    float lre = mag * cosf(th);
    float lim = mag * sinf(th);
    g_lre[h] = lre; g_lim[h] = lim;
    float ar = 1.f, ai = 0.f;
    for (int t = 0; t < T_CHUNK; t++) {
        float nr = ar * lre - ai * lim;
        ai = ar * lim + ai * lre;
        ar = nr;
    }
    g_lTre[h] = ar; g_lTim[h] = ai;
}

// ---------------- scan (stacked [L x 2048]: re | im), 2 channels per thread ----------------
__global__ void scan_chunks() {
    int i = blockIdx.x * blockDim.x + threadIdx.x;   // channel pair 0..511
    int c = blockIdx.y;
    int h = i * 2;
    float2 lre = *(float2*)&g_lre[h];
    float2 lim = *(float2*)&g_lim[h];
    float hr0 = 0.f, hi0 = 0.f, hr1 = 0.f, hi1 = 0.f;
#pragma unroll 4
    for (int t = 0; t < T_CHUNK; t++) {
        size_t row = (size_t)(c * T_CHUNK + t) * 2048;
        float2 br = __half22float2(*(__half2*)&g_Buh[row + h]);
        float2 bi = __half22float2(*(__half2*)&g_Buh[row + 1024 + h]);
        float nr0 = fmaf(lre.x, hr0, fmaf(-lim.x, hi0, br.x));
        float ni0 = fmaf(lre.x, hi0, fmaf(lim.x, hr0, bi.x));
        float nr1 = fmaf(lre.y, hr1, fmaf(-lim.y, hi1, br.y));
        float ni1 = fmaf(lre.y, hi1, fmaf(lim.y, hr1, bi.y));
        hr0 = nr0; hi0 = ni0; hr1 = nr1; hi1 = ni1;
    }
    *(float2*)&g_Ere[c * H_DIM + h] = make_float2(hr0, hr1);
    *(float2*)&g_Eim[c * H_DIM + h] = make_float2(hi0, hi1);
}

__global__ void scan_combine(float* __restrict__ out_head, int head_mode) {
    int h = blockIdx.x * blockDim.x + threadIdx.x;
    float lTre = g_lTre[h], lTim = g_lTim[h];
    float sr = 0.f, si = 0.f;
    for (int c = 0; c < N_CHUNK; c++) {
        g_Sre[c * H_DIM + h] = sr;
        g_Sim[c * H_DIM + h] = si;
        float er = g_Ere[c * H_DIM + h];
        float ei = g_Eim[c * H_DIM + h];
        float nr = fmaf(lTre, sr, fmaf(-lTim, si, er));
        float ni = fmaf(lTre, si, fmaf(lTim, sr, ei));
        sr = nr; si = ni;
    }
    if (head_mode == 1) {
        out_head[h] = sr;
    } else if (head_mode == 2) {
        out_head[2 * h]     = sr;
        out_head[2 * h + 1] = si;
    }
}

__global__ void scan_apply() {      // emits fp16 hidden state into g_Hh
    int i = blockIdx.x * blockDim.x + threadIdx.x;   // channel pair 0..511
    int c = blockIdx.y;
    int h = i * 2;
    float2 lre = *(float2*)&g_lre[h];
    float2 lim = *(float2*)&g_lim[h];
    float2 sr = *(float2*)&g_Sre[c * H_DIM + h];
    float2 si = *(float2*)&g_Sim[c * H_DIM + h];
    float hr0 = sr.x, hi0 = si.x, hr1 = sr.y, hi1 = si.y;
#pragma unroll 4
    for (int t = 0; t < T_CHUNK; t++) {
        size_t row = (size_t)(c * T_CHUNK + t) * 2048;
        float2 br = __half22float2(*(__half2*)&g_Buh[row + h]);
        float2 bi = __half22float2(*(__half2*)&g_Buh[row + 1024 + h]);
        float nr0 = fmaf(lre.x, hr0, fmaf(-lim.x, hi0, br.x));
        float ni0 = fmaf(lre.x, hi0, fmaf(lim.x, hr0, bi.x));
        float nr1 = fmaf(lre.y, hr1, fmaf(-lim.y, hi1, br.y));
        float ni1 = fmaf(lre.y, hi1, fmaf(lim.y, hr1, bi.y));
        hr0 = nr0; hi0 = ni0; hr1 = nr1; hi1 = ni1;
        *(__half2*)&g_Hh[row + h]        = __floats2half2_rn(hr0, hr1);
        *(__half2*)&g_Hh[row + 1024 + h] = __floats2half2_rn(hi0, hi1);
    }
}

// ---------------- launch ----------------
extern "C" void kernel_launch(void* const* d_in, const int* in_sizes, int n_in,
                              void* d_out, int out_size) {
    const float* x         = (const float*)d_in[0];
    const float* nu_log    = (const float*)d_in[1];
    const float* theta_log = (const float*)d_in[2];
    const float* gamma_log = (const float*)d_in[3];
    const float* Bre       = (const float*)d_in[4];
    const float* Bim       = (const float*)d_in[5];
    const float* Cre       = (const float*)d_in[6];
    const float* Cim       = (const float*)d_in[7];
    const float* Dp        = (const float*)d_in[8];

    float* out = (float*)d_out;
    long long head = (long long)out_size - (long long)L_SEQ * D_MOD;
    if (head < 0) head = 0;
    int head_mode = 0;
    if (head >= 2 * H_DIM)  head_mode = 2;
    else if (head >= H_DIM) head_mode = 1;
    float* out_head = out;
    float* out_y = out + head;

    __half *pxh, *pW1h, *pW2h, *pHh, *pBuh;
    cudaGetSymbolAddress((void**)&pxh,  g_xh);
    cudaGetSymbolAddress((void**)&pW1h, g_W1h);
    cudaGetSymbolAddress((void**)&pW2h, g_W2h);
    cudaGetSymbolAddress((void**)&pHh,  g_Hh);
    cudaGetSymbolAddress((void**)&pBuh, g_Buh);

    cudaFuncSetAttribute((const void*)mma_gemm<0,1>, cudaFuncAttributeMaxDynamicSharedMemorySize, SMEM_TOTAL);
    cudaFuncSetAttribute((const void*)mma_gemm<1,0>, cudaFuncAttributeMaxDynamicSharedMemorySize, SMEM_TOTAL);

    prep_params<<<H_DIM / 256, 256>>>(nu_log, theta_log);
    conv_x<<<(L_SEQ * D_MOD) / (256 * 4), 256>>>(x);
    prep_W1<<<2 * H_DIM, 256>>>(Bre, Bim, gamma_log);
    prep_W2<<<D_MOD, 256>>>(Cre, Cim);

    // GEMM1: Bu[16384 x 2048] (fp16) = x @ [B'_re ; B'_im]^T   (K=1024 halves)
    mma_gemm<0,1><<<dim3(L_SEQ / 128, 2048 / 128), 256, SMEM_TOTAL>>>(
        pxh, pW1h, pBuh, 1024, 2048, nullptr, nullptr);

    scan_chunks<<<dim3(H_DIM / 512, N_CHUNK), 256>>>();
    scan_combine<<<H_DIM / 256, 256>>>(out_head, head_mode);
    scan_apply<<<dim3(H_DIM / 512, N_CHUNK), 256>>>();

    // GEMM2: y = [Hre|Him] @ [Cre|-Cim]^T + Dp*x   (K=2048 halves)
    mma_gemm<1,0><<<dim3(L_SEQ / 128, 1024 / 128), 256, SMEM_TOTAL>>>(
        pHh, pW2h, out_y, 2048, 1024, Dp, x);
}